// round 7
// baseline (speedup 1.0000x reference)
#include <cuda_runtime.h>
#include <math.h>

#define FULLM 0xffffffffu
#define MINN 1e-15f
#define MAXNORM 0.996f        // (1 - 0.004) / sqrt(c), c = 1
#define ATANH_MAX 3.1063030f  // artanh(0.996)
#define ATANH_MAX2 9.6491187f // artanh(0.996)^2

// ---------------- device scratch ----------------
__device__ float g_p[24576 * 32];   // ball-mapped rows (3.1MB, L2-resident)
__device__ float g_lam[24576];      // artanh(|p|)/|p| per row

// ---------------- helpers ----------------
__device__ __forceinline__ float wredsum(float v) {
#pragma unroll
    for (int o = 16; o; o >>= 1) v += __shfl_xor_sync(FULLM, v, o);
    return v;
}
__device__ __forceinline__ void wredsum2(float& a, float& b) {
#pragma unroll
    for (int o = 16; o; o >>= 1) {
        a += __shfl_xor_sync(FULLM, a, o);
        b += __shfl_xor_sync(FULLM, b, o);
    }
}
__device__ __forceinline__ float tanh_fast(float x) {   // x >= 0, clip 15
    x = fminf(x, 15.f);
    float e = __expf(-2.f * x);
    return __fdividef(1.f - e, 1.f + e);
}
__device__ __forceinline__ float artanh_fast(float x) {
    x = fminf(fmaxf(x, -1.f + 1e-7f), 1.f - 1e-7f);
    return 0.5f * __logf(__fdividef(1.f + x, 1.f - x));
}
__device__ __forceinline__ void norm_inv(float s, float& n, float& inv) {
    s = fmaxf(s, 1e-30f);
    inv = __frsqrt_rn(s);
    n = s * inv;
}

// hyp bias proj(expmap0(b)); warp-collective, writes smem
template <int J>
__device__ __forceinline__ void make_hyp_bias(const float* b, float* hb, float* hbn2) {
    const int lane = threadIdx.x & 31;
    float v[J];
    float s = 0.f;
#pragma unroll
    for (int j = 0; j < J; j++) { v[j] = b[lane * J + j]; s += v[j] * v[j]; }
    float n, inv;
    norm_inv(wredsum(s), n, inv);
    float t = tanh_fast(n);
#pragma unroll
    for (int j = 0; j < J; j++) v[j] *= t * inv;
    float f = (t > MAXNORM) ? __fdividef(MAXNORM, t) : 1.f;
    float vn = fminf(t, MAXNORM);
#pragma unroll
    for (int j = 0; j < J; j++) hb[lane * J + j] = v[j] * f;
    if (lane == 0) *hbn2 = vn * vn;
}

// ---------------- kernel 1: gather + logmap0 + expmap0 + proj ----------------
// tasks t in [0, 24576): bid = t/6, k = t%6 (k==5 -> agent row). One warp/task.
__global__ void __launch_bounds__(256) k_gather(const float* __restrict__ in_nei,
                                                const float* __restrict__ in_feats) {
    const int tid = threadIdx.x, wid = tid >> 5, lane = tid & 31;
    const int t = blockIdx.x * 8 + wid;
    const int bid = t / 6;
    const int k = t - bid * 6;
    const float* fbase = in_feats + (bid >> 10) * (1024 * 32);

    float x = 0.f;
    if (k == 5) {
        float f = in_feats[bid * 32 + lane];
        float n, inv;
        norm_inv(wredsum(f * f), n, inv);
        x = __fdividef(artanh_fast(n), n) * f;
    } else {
        const float4* p4 = (const float4*)(in_nei + ((size_t)bid * 5 + k) * 1024);
        auto addc = [&](float w, int n) {
            if (w != 0.f) {   // warp-uniform (w broadcast)
                float f = fbase[n * 32 + lane];
                float nn, inv;
                norm_inv(wredsum(f * f), nn, inv);
                x = fmaf(w * __fdividef(artanh_fast(nn), nn), f, x);
            }
        };
#pragma unroll 1
        for (int pr = 0; pr < 4; pr++) {
            float4 a = p4[pr * 64 + lane];
            float4 b = p4[pr * 64 + 32 + lane];
            bool nz = (a.x != 0.f) || (a.y != 0.f) || (a.z != 0.f) || (a.w != 0.f) ||
                      (b.x != 0.f) || (b.y != 0.f) || (b.z != 0.f) || (b.w != 0.f);
            unsigned mk = __ballot_sync(FULLM, nz);
            if (mk) {
                while (mk) {
                    int src = __ffs(mk) - 1;
                    mk &= mk - 1u;
                    float ax = __shfl_sync(FULLM, a.x, src), ay = __shfl_sync(FULLM, a.y, src);
                    float az = __shfl_sync(FULLM, a.z, src), aw = __shfl_sync(FULLM, a.w, src);
                    float bx = __shfl_sync(FULLM, b.x, src), by = __shfl_sync(FULLM, b.y, src);
                    float bz = __shfl_sync(FULLM, b.z, src), bw = __shfl_sync(FULLM, b.w, src);
                    int na = pr * 256 + src * 4;
                    int nb = pr * 256 + 128 + src * 4;
                    addc(ax, na + 0); addc(ay, na + 1); addc(az, na + 2); addc(aw, na + 3);
                    addc(bx, nb + 0); addc(by, nb + 1); addc(bz, nb + 2); addc(bw, nb + 3);
                }
                break;   // one-hot row: first nonzero pair is the only one
            }
        }
    }
    // expmap0 + proj on the fly (latency-bound kernel: ALU is free)
    float n, inv;
    norm_inv(wredsum(x * x), n, inv);
    float tt = tanh_fast(n);
    float f = (tt > MAXNORM) ? __fdividef(MAXNORM, tt) : 1.f;
    float pnr = fminf(tt, MAXNORM);
    g_p[(size_t)t * 32 + lane] = tt * inv * f * x;
    if (lane == 0)
        g_lam[t] = (pnr > 1e-6f) ? __fdividef(artanh_fast(pnr), pnr) : 1.f;
}

// ---------------- kernel 2: per-bid pipeline (heads + attention + W2) ----------------
// 8 warps/block, ONE bid per warp, grid = 512 -> 3 blocks/SM resident.
__global__ void __launch_bounds__(256, 3) k_bidpipe(const float* __restrict__ W1,
                                                    const float* __restrict__ b1,
                                                    const float* __restrict__ W2,
                                                    const float* __restrict__ b2,
                                                    float* __restrict__ outp,
                                                    float* __restrict__ attr) {
    extern __shared__ float sm[];
    float* w1t = sm;                    // 32*161  [d*161 + m]
    float* w2t = w1t + 5152;            // 32*33   [d*33 + m]
    float* hb1 = w2t + 1056;            // 160
    float* hb2 = hb1 + 160;             // 32
    float* hbn = hb2 + 32;              // 2
    float* slab = hbn + 2;              // 8 * 1008  [wid][r*168 + j*33 + d]
    float* attws = slab + 8 * 1008;     // 8 * 32

    const int tid = threadIdx.x, wid = tid >> 5, lane = tid & 31;

    if (wid == 0) {
        make_hyp_bias<5>(b1, hb1, &hbn[0]);
    } else if (wid == 1) {
        make_hyp_bias<1>(b2, hb2, &hbn[1]);
    } else {
        for (int i = tid - 64; i < 6208; i += 192) {
            if (i < 5152) {
                int m = i >> 5, d = i & 31;
                w1t[d * 161 + m] = W1[i];
            } else {
                int j = i - 5152;
                int m = j >> 5, d = j & 31;
                w2t[d * 33 + m] = W2[j];
            }
        }
    }
    __syncthreads();

    const float hbn2 = hbn[0];
    float* myslab = slab + wid * 1008;
    float* attw = attws + wid * 32;
    float hbl[5];
#pragma unroll
    for (int j = 0; j < 5; j++) hbl[j] = hb1[lane * 5 + j];

    const int bid = blockIdx.x * 8 + wid;

    // ---- load 6 ball points + lambdas ----
    float p[6], lam[6];
#pragma unroll
    for (int r = 0; r < 6; r++) {
        p[r] = g_p[(size_t)(bid * 6 + r) * 32 + lane];
        lam[r] = g_lam[bid * 6 + r];
    }
    // ---- batched matvec: mx[r][j] = sum_d W1[lane*5+j][d] * p[r][d] ----
    float mx[6][5];
#pragma unroll
    for (int r = 0; r < 6; r++)
#pragma unroll
        for (int j = 0; j < 5; j++) mx[r][j] = 0.f;
#pragma unroll
    for (int d = 0; d < 32; d++) {
        float w0 = w1t[d * 161 + lane * 5 + 0];
        float w1 = w1t[d * 161 + lane * 5 + 1];
        float w2 = w1t[d * 161 + lane * 5 + 2];
        float w3 = w1t[d * 161 + lane * 5 + 3];
        float w4 = w1t[d * 161 + lane * 5 + 4];
#pragma unroll
        for (int r = 0; r < 6; r++) {
            float pd = __shfl_sync(FULLM, p[r], d);
            mx[r][0] = fmaf(w0, pd, mx[r][0]);
            mx[r][1] = fmaf(w1, pd, mx[r][1]);
            mx[r][2] = fmaf(w2, pd, mx[r][2]);
            mx[r][3] = fmaf(w3, pd, mx[r][3]);
            mx[r][4] = fmaf(w4, pd, mx[r][4]);
        }
    }
    // ---- per-row epilogue (2 reduction rounds, 2 transcendentals, no ballots) ----
#pragma unroll
    for (int r = 0; r < 6; r++) {
        float s2 = 0.f, q = 0.f;
#pragma unroll
        for (int j = 0; j < 5; j++) {
            s2 = fmaf(mx[r][j], mx[r][j], s2);
            q = fmaf(mx[r][j], hbl[j], q);
        }
        wredsum2(s2, q);                       // dual interleaved butterfly
        float zf = (s2 > 0.f) ? 1.f : 0.f;     // all(mx==0) <=> s2==0 (warp-uniform)
        float mxn, inv2;
        norm_inv(s2, mxn, inv2);
        float t2 = tanh_fast(mxn * lam[r]);
        float rn = zf * t2;
        float fpr = (rn > MAXNORM) ? __fdividef(MAXNORM, rn) : 1.f;
        float sc = zf * t2 * inv2 * fpr;       // res = sc * mx
        float xy = sc * q;                     // <res, hb>
        float rp = fminf(rn, MAXNORM);
        float x2 = rp * rp;                    // |res|^2 analytic
        float num_a = 1.f + 2.f * xy + hbn2;
        float num_b = 1.f - x2;
        float rden = __fdividef(1.f, fmaxf(1.f + 2.f * xy + x2 * hbn2, MINN));
        // |h|^2 analytic
        float s3 = rden * rden *
                   (num_a * num_a * x2 + 2.f * num_a * num_b * xy + num_b * num_b * hbn2);
        float hn = sqrtf(s3);
        float th = (hn > 1e-6f)
                       ? __fdividef(artanh_fast(fminf(hn, MAXNORM)), hn)
                       : 1.f;                  // proj + logmap0 combined
        float xt[5];
        float s4 = 0.f;
#pragma unroll
        for (int j = 0; j < 5; j++) {
            float h = (num_a * sc * mx[r][j] + num_b * hbl[j]) * rden;
            xt[j] = fmaxf(th * h, 0.f);
            s4 = fmaf(xt[j], xt[j], s4);
        }
        s4 = wredsum(s4);
        // logmap0(proj(expmap0(xt))) = xt unless |expmap0(xt)| > MAXNORM
        float oc = (s4 > ATANH_MAX2) ? ATANH_MAX * __frsqrt_rn(s4) : 1.f;
#pragma unroll
        for (int j = 0; j < 5; j++) myslab[r * 168 + j * 33 + lane] = oc * xt[j];
    }
    __syncwarp();

    // ---- attention: lane -> (hh = lane/5, kk = lane%5) ----
    const int hh = lane / 5, kk = lane - hh * 5;
    float a_un = 0.f;
    if (lane < 25) {
        const float* ag = myslab + 5 * 168 + hh * 33;
        const float* ng = myslab + kk * 168 + hh * 33;
        float s = 0.f;
#pragma unroll
        for (int d = 0; d < 32; d++) s = fmaf(ag[d], ng[d], s);
        a_un = s;
    }
    attw[lane] = a_un;
    __syncwarp();
    float aval = 0.f;
    if (lane < 25) {
        float m = -3.4e38f;
#pragma unroll
        for (int k2 = 0; k2 < 5; k2++) m = fmaxf(m, attw[hh * 5 + k2]);
        float se = 0.f;
#pragma unroll
        for (int k2 = 0; k2 < 5; k2++) se += __expf(attw[hh * 5 + k2] - m);
        aval = __expf(a_un - m) * __fdividef(1.f, se);
        attr[(size_t)bid * 25 + lane] = aval;
    }
    attw[lane] = aval;
    __syncwarp();

    float o = 0.f;
#pragma unroll
    for (int h2 = 0; h2 < 5; h2++)
#pragma unroll
        for (int k2 = 0; k2 < 5; k2++)
            o = fmaf(attw[h2 * 5 + k2], myslab[k2 * 168 + h2 * 33 + lane], o);
    o *= 0.2f;

    // ---- final W2 layer (ends with expmap0+proj; no collapse) ----
    {
        const float hb2l = hb2[lane];
        const float hbn2b = hbn[1];
        float n, inv;
        norm_inv(wredsum(o * o), n, inv);
        float t = tanh_fast(n);
        float f = (t > MAXNORM) ? __fdividef(MAXNORM, t) : 1.f;
        float pp = t * inv * o * f;
        float ppn = fminf(t, MAXNORM);
        float lamb = (ppn > 1e-6f) ? __fdividef(artanh_fast(ppn), ppn) : 1.f;
        float mxv = 0.f;
#pragma unroll
        for (int d = 0; d < 32; d++) {
            float pd = __shfl_sync(FULLM, pp, d);
            mxv = fmaf(w2t[d * 33 + lane], pd, mxv);
        }
        float s2 = mxv * mxv, q = mxv * hb2l;
        wredsum2(s2, q);
        float zf = (s2 > 0.f) ? 1.f : 0.f;
        float mxn, inv2;
        norm_inv(s2, mxn, inv2);
        float t2 = tanh_fast(mxn * lamb);
        float rn = zf * t2;
        float fpr = (rn > MAXNORM) ? __fdividef(MAXNORM, rn) : 1.f;
        float sc = zf * t2 * inv2 * fpr;
        float xy = sc * q;
        float rp = fminf(rn, MAXNORM);
        float x2 = rp * rp;
        float num_a = 1.f + 2.f * xy + hbn2b;
        float num_b = 1.f - x2;
        float rden = __fdividef(1.f, fmaxf(1.f + 2.f * xy + x2 * hbn2b, MINN));
        float s3 = rden * rden *
                   (num_a * num_a * x2 + 2.f * num_a * num_b * xy + num_b * num_b * hbn2b);
        float hn = sqrtf(s3);
        float th = (hn > 1e-6f)
                       ? __fdividef(artanh_fast(fminf(hn, MAXNORM)), hn)
                       : 1.f;
        float h = (num_a * sc * mxv + num_b * hb2l) * rden;
        float xt = fmaxf(th * h, 0.f);
        float tn, inv4;
        norm_inv(wredsum(xt * xt), tn, inv4);
        float t4 = tanh_fast(tn);
        float fo = (t4 > MAXNORM) ? __fdividef(MAXNORM, t4) : 1.f;
        outp[(size_t)bid * 32 + lane] = t4 * inv4 * fo * xt;
    }
}

extern "C" void kernel_launch(void* const* d_in, const int* in_sizes, int n_in,
                              void* d_out, int out_size) {
    const float* in_feats = (const float*)d_in[0];
    const float* in_nei   = (const float*)d_in[1];
    const float* W1       = (const float*)d_in[2];
    const float* b1       = (const float*)d_in[3];
    const float* W2       = (const float*)d_in[4];
    const float* b2       = (const float*)d_in[5];
    float* outp = (float*)d_out;
    float* attr = outp + 4 * 1024 * 32;   // out first, att_record second

    const int smem_bytes = (5152 + 1056 + 160 + 32 + 2 + 8 * 1008 + 8 * 32) * 4;
    cudaFuncSetAttribute(k_bidpipe, cudaFuncAttributeMaxDynamicSharedMemorySize, smem_bytes);

    k_gather<<<3072, 256>>>(in_nei, in_feats);
    k_bidpipe<<<512, 256, smem_bytes>>>(W1, b1, W2, b2, outp, attr);
}

// round 8
// speedup vs baseline: 1.0836x; 1.0836x over previous
#include <cuda_runtime.h>
#include <math.h>

#define FULLM 0xffffffffu
#define MINN 1e-15f
#define MAXNORM 0.996f        // (1 - 0.004) / sqrt(c), c = 1
#define ATANH_MAX 3.1063030f  // artanh(0.996)
#define ATANH_MAX2 9.6491187f // artanh(0.996)^2

// ---------------- device scratch ----------------
__device__ float g_p[24576 * 32];   // ball-mapped rows (3.1MB, L2-resident)
__device__ float g_lam[24576];      // artanh(|p|)/|p| per row

// ---------------- helpers ----------------
__device__ __forceinline__ float wredsum(float v) {
#pragma unroll
    for (int o = 16; o; o >>= 1) v += __shfl_xor_sync(FULLM, v, o);
    return v;
}
__device__ __forceinline__ void wredsum2(float& a, float& b) {
#pragma unroll
    for (int o = 16; o; o >>= 1) {
        a += __shfl_xor_sync(FULLM, a, o);
        b += __shfl_xor_sync(FULLM, b, o);
    }
}
__device__ __forceinline__ float tanh_fast(float x) {   // x >= 0, clip 15
    x = fminf(x, 15.f);
    float e = __expf(-2.f * x);
    return __fdividef(1.f - e, 1.f + e);
}
__device__ __forceinline__ float artanh_fast(float x) {
    x = fminf(fmaxf(x, -1.f + 1e-7f), 1.f - 1e-7f);
    return 0.5f * __logf(__fdividef(1.f + x, 1.f - x));
}
__device__ __forceinline__ void norm_inv(float s, float& n, float& inv) {
    s = fmaxf(s, 1e-30f);
    inv = __frsqrt_rn(s);
    n = s * inv;
}

// hyp bias proj(expmap0(b)); warp-collective, writes smem
template <int J>
__device__ __forceinline__ void make_hyp_bias(const float* b, float* hb, float* hbn2) {
    const int lane = threadIdx.x & 31;
    float v[J];
    float s = 0.f;
#pragma unroll
    for (int j = 0; j < J; j++) { v[j] = b[lane * J + j]; s += v[j] * v[j]; }
    float n, inv;
    norm_inv(wredsum(s), n, inv);
    float t = tanh_fast(n);
#pragma unroll
    for (int j = 0; j < J; j++) v[j] *= t * inv;
    float f = (t > MAXNORM) ? __fdividef(MAXNORM, t) : 1.f;
    float vn = fminf(t, MAXNORM);
#pragma unroll
    for (int j = 0; j < J; j++) hb[lane * J + j] = v[j] * f;
    if (lane == 0) *hbn2 = vn * vn;
}

// ---------------- kernel 1: gather + logmap0 + expmap0 + proj ----------------
__global__ void __launch_bounds__(256) k_gather(const float* __restrict__ in_nei,
                                                const float* __restrict__ in_feats) {
    const int tid = threadIdx.x, wid = tid >> 5, lane = tid & 31;
    const int t = blockIdx.x * 8 + wid;
    const int bid = t / 6;
    const int k = t - bid * 6;
    const float* fbase = in_feats + (bid >> 10) * (1024 * 32);

    float x = 0.f;
    if (k == 5) {
        float f = in_feats[bid * 32 + lane];
        float n, inv;
        norm_inv(wredsum(f * f), n, inv);
        x = __fdividef(artanh_fast(n), n) * f;
    } else {
        const float4* p4 = (const float4*)(in_nei + ((size_t)bid * 5 + k) * 1024);
        auto addc = [&](float w, int n) {
            if (w != 0.f) {   // warp-uniform (w broadcast)
                float f = fbase[n * 32 + lane];
                float nn, inv;
                norm_inv(wredsum(f * f), nn, inv);
                x = fmaf(w * __fdividef(artanh_fast(nn), nn), f, x);
            }
        };
#pragma unroll 1
        for (int pr = 0; pr < 4; pr++) {
            float4 a = p4[pr * 64 + lane];
            float4 b = p4[pr * 64 + 32 + lane];
            bool nz = (a.x != 0.f) || (a.y != 0.f) || (a.z != 0.f) || (a.w != 0.f) ||
                      (b.x != 0.f) || (b.y != 0.f) || (b.z != 0.f) || (b.w != 0.f);
            unsigned mk = __ballot_sync(FULLM, nz);
            if (mk) {
                while (mk) {
                    int src = __ffs(mk) - 1;
                    mk &= mk - 1u;
                    float ax = __shfl_sync(FULLM, a.x, src), ay = __shfl_sync(FULLM, a.y, src);
                    float az = __shfl_sync(FULLM, a.z, src), aw = __shfl_sync(FULLM, a.w, src);
                    float bx = __shfl_sync(FULLM, b.x, src), by = __shfl_sync(FULLM, b.y, src);
                    float bz = __shfl_sync(FULLM, b.z, src), bw = __shfl_sync(FULLM, b.w, src);
                    int na = pr * 256 + src * 4;
                    int nb = pr * 256 + 128 + src * 4;
                    addc(ax, na + 0); addc(ay, na + 1); addc(az, na + 2); addc(aw, na + 3);
                    addc(bx, nb + 0); addc(by, nb + 1); addc(bz, nb + 2); addc(bw, nb + 3);
                }
                break;   // one-hot row: first nonzero pair is the only one
            }
        }
    }
    float n, inv;
    norm_inv(wredsum(x * x), n, inv);
    float tt = tanh_fast(n);
    float f = (tt > MAXNORM) ? __fdividef(MAXNORM, tt) : 1.f;
    float pnr = fminf(tt, MAXNORM);
    g_p[(size_t)t * 32 + lane] = tt * inv * f * x;
    if (lane == 0)
        g_lam[t] = (pnr > 1e-6f) ? __fdividef(artanh_fast(pnr), pnr) : 1.f;
}

// ---------------- kernel 2: per-bid pipeline (heads + attention + W2) ----------------
// 8 warps/block, one bid per warp, grid = 512.
__global__ void __launch_bounds__(256, 3) k_bidpipe(const float* __restrict__ W1,
                                                    const float* __restrict__ b1,
                                                    const float* __restrict__ W2,
                                                    const float* __restrict__ b2,
                                                    float* __restrict__ outp,
                                                    float* __restrict__ attr) {
    extern __shared__ float sm[];
    float* w1t = sm;                    // 32*161  [d*161 + m]
    float* w2t = w1t + 5152;            // 32*33   [d*33 + m]
    float* hb1 = w2t + 1056;            // 160
    float* hb2 = hb1 + 160;             // 32
    float* hbn = hb2 + 32;              // 2
    float* slab = hbn + 2;              // 8 * 1008  [wid][r*168 + j*33 + d]
    float* attws = slab + 8 * 1008;     // 8 * 32

    const int tid = threadIdx.x, wid = tid >> 5, lane = tid & 31;

    if (wid == 0) {
        make_hyp_bias<5>(b1, hb1, &hbn[0]);
    } else if (wid == 1) {
        make_hyp_bias<1>(b2, hb2, &hbn[1]);
    } else {
        for (int i = tid - 64; i < 6208; i += 192) {
            if (i < 5152) {
                int m = i >> 5, d = i & 31;
                w1t[d * 161 + m] = W1[i];
            } else {
                int j = i - 5152;
                int m = j >> 5, d = j & 31;
                w2t[d * 33 + m] = W2[j];
            }
        }
    }
    __syncthreads();

    const float hbn2 = hbn[0];
    float* myslab = slab + wid * 1008;
    float* attw = attws + wid * 32;
    float hbl[5];
#pragma unroll
    for (int j = 0; j < 5; j++) hbl[j] = hb1[lane * 5 + j];

    const int bid = blockIdx.x * 8 + wid;

    // ---- load 6 ball points ----
    float p[6];
#pragma unroll
    for (int r = 0; r < 6; r++) p[r] = g_p[(size_t)(bid * 6 + r) * 32 + lane];

    // ---- batched matvec: mx[r][j] = sum_d W1[lane*5+j][d] * p[r][d] ----
    float mx[6][5];
#pragma unroll
    for (int r = 0; r < 6; r++)
#pragma unroll
        for (int j = 0; j < 5; j++) mx[r][j] = 0.f;
#pragma unroll
    for (int d = 0; d < 32; d++) {
        float w0 = w1t[d * 161 + lane * 5 + 0];
        float w1 = w1t[d * 161 + lane * 5 + 1];
        float w2 = w1t[d * 161 + lane * 5 + 2];
        float w3 = w1t[d * 161 + lane * 5 + 3];
        float w4 = w1t[d * 161 + lane * 5 + 4];
#pragma unroll
        for (int r = 0; r < 6; r++) {
            float pd = __shfl_sync(FULLM, p[r], d);
            mx[r][0] = fmaf(w0, pd, mx[r][0]);
            mx[r][1] = fmaf(w1, pd, mx[r][1]);
            mx[r][2] = fmaf(w2, pd, mx[r][2]);
            mx[r][3] = fmaf(w3, pd, mx[r][3]);
            mx[r][4] = fmaf(w4, pd, mx[r][4]);
        }
    }

    // ---- per-lane partials for all 6 rows ----
    float s2[6], q[6];
#pragma unroll
    for (int r = 0; r < 6; r++) {
        float a = 0.f, b = 0.f;
#pragma unroll
        for (int j = 0; j < 5; j++) {
            a = fmaf(mx[r][j], mx[r][j], a);
            b = fmaf(mx[r][j], hbl[j], b);
        }
        s2[r] = a; q[r] = b;
    }
    // ---- ONE batched butterfly for all 12 sums (12-way ILP) ----
#pragma unroll
    for (int o = 16; o; o >>= 1) {
#pragma unroll
        for (int r = 0; r < 6; r++) {
            s2[r] += __shfl_xor_sync(FULLM, s2[r], o);
            q[r]  += __shfl_xor_sync(FULLM, q[r], o);
        }
    }
    // ---- lane-parallel scalar chain: lane r handles row r (r < 6) ----
    float s2l = s2[0], ql = q[0];
#pragma unroll
    for (int r = 1; r < 6; r++)
        if (lane == r) { s2l = s2[r]; ql = q[r]; }
    float laml = g_lam[bid * 6 + ((lane < 6) ? lane : 0)];

    float alpha, beta;
    {
        float zf = (s2l > 0.f) ? 1.f : 0.f;
        float mxn, inv2;
        norm_inv(s2l, mxn, inv2);
        float t2 = tanh_fast(mxn * laml);
        float rn = zf * t2;
        float fpr = (rn > MAXNORM) ? __fdividef(MAXNORM, rn) : 1.f;
        float sc = zf * t2 * inv2 * fpr;       // res = sc * mx
        float xy = sc * ql;                    // <res, hb>
        float rp = fminf(rn, MAXNORM);
        float x2 = rp * rp;                    // |res|^2 analytic
        float num_a = 1.f + 2.f * xy + hbn2;
        float num_b = 1.f - x2;
        float rden = __fdividef(1.f, fmaxf(1.f + 2.f * xy + x2 * hbn2, MINN));
        float s3 = rden * rden *
                   (num_a * num_a * x2 + 2.f * num_a * num_b * xy + num_b * num_b * hbn2);
        float hn = sqrtf(s3);
        float th = (hn > 1e-6f)
                       ? __fdividef(artanh_fast(fminf(hn, MAXNORM)), hn)
                       : 1.f;                  // proj + logmap0 combined
        alpha = th * num_a * sc * rden;        // h-scale on mx
        beta  = th * num_b * rden;             // h-scale on hb
    }
    // broadcast the two per-row coefficients
    float A[6], B[6];
#pragma unroll
    for (int r = 0; r < 6; r++) {
        A[r] = __shfl_sync(FULLM, alpha, r);
        B[r] = __shfl_sync(FULLM, beta, r);
    }
    // ---- xt = relu(.), batched s4 reduction, store ----
    float s4[6];
#pragma unroll
    for (int r = 0; r < 6; r++) {
        float a = 0.f;
#pragma unroll
        for (int j = 0; j < 5; j++) {
            float xt = fmaxf(fmaf(A[r], mx[r][j], B[r] * hbl[j]), 0.f);
            mx[r][j] = xt;                     // reuse registers
            a = fmaf(xt, xt, a);
        }
        s4[r] = a;
    }
#pragma unroll
    for (int o = 16; o; o >>= 1)
#pragma unroll
        for (int r = 0; r < 6; r++) s4[r] += __shfl_xor_sync(FULLM, s4[r], o);
#pragma unroll
    for (int r = 0; r < 6; r++) {
        // logmap0(proj(expmap0(xt))): identity unless tanh(|xt|) > MAXNORM
        float oc = fminf(1.f, ATANH_MAX * __frsqrt_rn(fmaxf(s4[r], 1e-30f)));
#pragma unroll
        for (int j = 0; j < 5; j++) myslab[r * 168 + j * 33 + lane] = oc * mx[r][j];
    }
    __syncwarp();

    // ---- attention: lane -> (hh = lane/5, kk = lane%5) ----
    const int hh = lane / 5, kk = lane - hh * 5;
    float a_un = 0.f;
    if (lane < 25) {
        const float* ag = myslab + 5 * 168 + hh * 33;
        const float* ng = myslab + kk * 168 + hh * 33;
        float s = 0.f;
#pragma unroll
        for (int d = 0; d < 32; d++) s = fmaf(ag[d], ng[d], s);
        a_un = s;
    }
    attw[lane] = a_un;
    __syncwarp();
    float aval = 0.f;
    if (lane < 25) {
        float m = -3.4e38f;
#pragma unroll
        for (int k2 = 0; k2 < 5; k2++) m = fmaxf(m, attw[hh * 5 + k2]);
        float se = 0.f;
#pragma unroll
        for (int k2 = 0; k2 < 5; k2++) se += __expf(attw[hh * 5 + k2] - m);
        aval = __expf(a_un - m) * __fdividef(1.f, se);
        attr[(size_t)bid * 25 + lane] = aval;
    }
    attw[lane] = aval;
    __syncwarp();

    float o = 0.f;
#pragma unroll
    for (int h2 = 0; h2 < 5; h2++)
#pragma unroll
        for (int k2 = 0; k2 < 5; k2++)
            o = fmaf(attw[h2 * 5 + k2], myslab[k2 * 168 + h2 * 33 + lane], o);
    o *= 0.2f;

    // ---- final W2 layer (ends with expmap0+proj) ----
    {
        const float hb2l = hb2[lane];
        const float hbn2b = hbn[1];
        float n, inv;
        norm_inv(wredsum(o * o), n, inv);
        float t = tanh_fast(n);
        float f = (t > MAXNORM) ? __fdividef(MAXNORM, t) : 1.f;
        float pp = t * inv * o * f;
        float ppn = fminf(t, MAXNORM);
        float lamb = (ppn > 1e-6f) ? __fdividef(artanh_fast(ppn), ppn) : 1.f;
        float mxv = 0.f;
#pragma unroll
        for (int d = 0; d < 32; d++) {
            float pd = __shfl_sync(FULLM, pp, d);
            mxv = fmaf(w2t[d * 33 + lane], pd, mxv);
        }
        float s2w = mxv * mxv, qw = mxv * hb2l;
        wredsum2(s2w, qw);
        float zf = (s2w > 0.f) ? 1.f : 0.f;
        float mxn, inv2;
        norm_inv(s2w, mxn, inv2);
        float t2 = tanh_fast(mxn * lamb);
        float rn = zf * t2;
        float fpr = (rn > MAXNORM) ? __fdividef(MAXNORM, rn) : 1.f;
        float sc = zf * t2 * inv2 * fpr;
        float xy = sc * qw;
        float rp = fminf(rn, MAXNORM);
        float x2 = rp * rp;
        float num_a = 1.f + 2.f * xy + hbn2b;
        float num_b = 1.f - x2;
        float rden = __fdividef(1.f, fmaxf(1.f + 2.f * xy + x2 * hbn2b, MINN));
        float s3 = rden * rden *
                   (num_a * num_a * x2 + 2.f * num_a * num_b * xy + num_b * num_b * hbn2b);
        float hn = sqrtf(s3);
        float th = (hn > 1e-6f)
                       ? __fdividef(artanh_fast(fminf(hn, MAXNORM)), hn)
                       : 1.f;
        float h = (num_a * sc * mxv + num_b * hb2l) * rden;
        float xt = fmaxf(th * h, 0.f);
        float tn, inv4;
        norm_inv(wredsum(xt * xt), tn, inv4);
        float t4 = tanh_fast(tn);
        float fo = (t4 > MAXNORM) ? __fdividef(MAXNORM, t4) : 1.f;
        outp[(size_t)bid * 32 + lane] = t4 * inv4 * fo * xt;
    }
}

extern "C" void kernel_launch(void* const* d_in, const int* in_sizes, int n_in,
                              void* d_out, int out_size) {
    const float* in_feats = (const float*)d_in[0];
    const float* in_nei   = (const float*)d_in[1];
    const float* W1       = (const float*)d_in[2];
    const float* b1       = (const float*)d_in[3];
    const float* W2       = (const float*)d_in[4];
    const float* b2       = (const float*)d_in[5];
    float* outp = (float*)d_out;
    float* attr = outp + 4 * 1024 * 32;   // out first, att_record second

    const int smem_bytes = (5152 + 1056 + 160 + 32 + 2 + 8 * 1008 + 8 * 32) * 4;
    cudaFuncSetAttribute(k_bidpipe, cudaFuncAttributeMaxDynamicSharedMemorySize, smem_bytes);

    k_gather<<<3072, 256>>>(in_nei, in_feats);
    k_bidpipe<<<512, 256, smem_bytes>>>(W1, b1, W2, b2, outp, attr);
}